// round 16
// baseline (speedup 1.0000x reference)
#include <cuda_runtime.h>
#include <cuda_fp16.h>
#include <math.h>

#define BATCH 512
#define NUM_CAPS 181
#define IN_CAPS 96
#define CAPS_DIM 16
#define KSEL 4
#define OI (NUM_CAPS * IN_CAPS)          // 17376
#define UHAT_TILE (IN_CAPS * CAPS_DIM)   // 1536
#define MLP_ROWS (BATCH * KSEL)          // 2048
#define NTOT (NUM_CAPS * CAPS_DIM)       // 2896

// transposed fp16 MLP weight offsets inside d_wt
#define OFF2 0
#define OFF3 786432
#define OFF4 1179648
#define OFF5 1441792
#define OFFH 1572864
#define WT_TOTAL 1605632

// paired conv-weight offsets inside d_wp (ull units)
#define WP2_OFF 0         // w2: 128*64*4
#define WP3_OFF 32768     // w3: 256*128*4
#define WPP_OFF 163840    // pw: 96*256*4
#define WP_TOTAL 262144

typedef unsigned long long ull;

// ---------------- scratch (device globals; no allocation allowed) -------------
__device__ __half d_uh[IN_CAPS * BATCH * CAPS_DIM];                // u fp16, [i][b][k]
__device__ __half d_vh[(size_t)IN_CAPS * NTOT * CAPS_DIM];         // W repack, [i][n][k]
__device__ __half d_uhat[(size_t)BATCH * NUM_CAPS * IN_CAPS * CAPS_DIM]; // 285 MB
__device__ float  d_bl[BATCH * OI];
__device__ float2 d_ms[BATCH * IN_CAPS];
__device__ float  d_x[BATCH * NUM_CAPS * CAPS_DIM];
__device__ int    d_idx[BATCH * KSEL];
__device__ float  d_g[MLP_ROWS * CAPS_DIM];
__device__ __half d_m0h[MLP_ROWS * 1024];
__device__ __half d_m1h[MLP_ROWS * 1024];
__device__ __half d_wt[WT_TOTAL];
__device__ ull    d_wp[WP_TOTAL];                                  // paired conv weights

__device__ __forceinline__ float gelu_f(float x) {
    return 0.5f * x * (1.0f + erff(x * 0.70710678118654752f));
}

// ---------------- f32x2 packed helpers ----------------------------------------
__device__ __forceinline__ ull pk2(float v) {
    ull r; asm("mov.b64 %0, {%1, %1};" : "=l"(r) : "f"(v)); return r;
}
__device__ __forceinline__ ull pkf(float lo, float hi) {
    ull r; asm("mov.b64 %0, {%1, %2};" : "=l"(r) : "f"(lo), "f"(hi)); return r;
}
#define UPK(V, LO, HI) asm("mov.b64 {%0, %1}, %2;" : "=f"(LO), "=f"(HI) : "l"(V))
#define FMA2(ACC, A, B) asm("fma.rn.f32x2 %0, %1, %2, %0;" : "+l"(ACC) : "l"(A), "l"(B))

// ---------------- 0) repacks ----------------------------------------------------
__global__ void wrepack_kernel(const float* __restrict__ capsW) {
    int idx = blockIdx.x * 256 + threadIdx.x;
    if (idx >= NUM_CAPS * 1536) return;
    int o = idx / 1536, r = idx % 1536, i = r >> 4, d = r & 15;
    const float* src = capsW + ((size_t)(o * 96 + i) * 16 + d) * 16;
    __half* dst = d_vh + ((size_t)i * NTOT + o * 16 + d) * 16;
    #pragma unroll
    for (int k = 0; k < 16; k++) dst[k] = __float2half(src[k]);
}

// tiled transpose: W[k][n] f32 -> Wt[n][k] f16, coalesced both sides
__global__ void wtrepack_kernel(const float* __restrict__ src, int Kd, int N, int off) {
    __shared__ float tile[32][33];
    const int kb = blockIdx.x * 32, nb = blockIdx.y * 32;
    const int tx = threadIdx.x & 31, ty = threadIdx.x >> 5;   // 256 thr: ty 0..7
    #pragma unroll
    for (int j = ty; j < 32; j += 8)
        tile[j][tx] = src[(size_t)(kb + j) * N + nb + tx];
    __syncthreads();
    #pragma unroll
    for (int j = ty; j < 32; j += 8)
        d_wt[off + (size_t)(nb + j) * Kd + kb + tx] = __float2half(tile[tx][j]);
}

// duplicate-pair conv weights (same linear order as source arrays)
__global__ void cwpack_kernel(const float* __restrict__ w2,
                              const float* __restrict__ w3,
                              const float* __restrict__ pw) {
    int idx = blockIdx.x * 256 + threadIdx.x;
    if (idx >= WP_TOTAL) return;
    float v;
    if (idx < WP3_OFF)       v = w2[idx];
    else if (idx < WPP_OFF)  v = w3[idx - WP3_OFF];
    else                     v = pw[idx - WPP_OFF];
    d_wp[idx] = pk2(v);
}

// ---------------- 1) conv stack: 2 images/block, f32x2 packed -------------------
#define CONV_SMEM ((384 + 12800 + 12800) * 4)

#define LDP8(d, p) do{ \
    ulonglong2 _a = *(const ulonglong2*)(p);        ulonglong2 _b = *(const ulonglong2*)((p)+4); \
    ulonglong2 _c = *(const ulonglong2*)((p)+8);    ulonglong2 _e = *(const ulonglong2*)((p)+12); \
    d[0]=_a.x; d[1]=_a.y; d[2]=_b.x; d[3]=_b.y; d[4]=_c.x; d[5]=_c.y; d[6]=_e.x; d[7]=_e.y; }while(0)

#define LDP6(d, p) do{ \
    ulonglong2 _a = *(const ulonglong2*)(p);        ulonglong2 _b = *(const ulonglong2*)((p)+4); \
    ulonglong2 _c = *(const ulonglong2*)((p)+8); \
    d[0]=_a.x; d[1]=_a.y; d[2]=_b.x; d[3]=_b.y; d[4]=_c.x; d[5]=_c.y; }while(0)

#define LDP5(d, p) do{ \
    d[0]=*(const ull*)(p);     d[1]=*(const ull*)((p)+2); d[2]=*(const ull*)((p)+4); \
    d[3]=*(const ull*)((p)+6); d[4]=*(const ull*)((p)+8); }while(0)

#define LDW4 \
    ulonglong2 _wa = *(const ulonglong2*)wp; ulonglong2 _wb = *(const ulonglong2*)(wp + 2); \
    ull wxx = _wa.x, wyy = _wa.y, wzz = _wb.x, www = _wb.y

#define CROW2(top, bot, acc, yy, W) do{ \
    _Pragma("unroll") \
    for (int _x = 0; _x < (W); _x++){ \
        FMA2(acc[(yy)*(W)+_x], top[_x],     wxx); \
        FMA2(acc[(yy)*(W)+_x], top[_x + 1], wyy); \
        FMA2(acc[(yy)*(W)+_x], bot[_x],     wzz); \
        FMA2(acc[(yy)*(W)+_x], bot[_x + 1], www); } }while(0)

__global__ __launch_bounds__(256, 2) void conv_stack_kernel(
        const float* __restrict__ scm,
        const float* __restrict__ w1, const float* __restrict__ b1,
        const float* __restrict__ b2, const float* __restrict__ b3,
        const float* __restrict__ pb) {
    extern __shared__ float smem[];
    float* s_in = smem;            // 384
    float* Y    = smem + 384;      // 12800
    float* X    = smem + 13184;    // 12800
    const int t = threadIdx.x, b0 = blockIdx.x * 2;

    for (int i = t; i < 384; i += 256)
        s_in[i] = scm[(size_t)(b0 + (i & 1)) * 192 + (i >> 1)];
    __syncthreads();

    // conv1 (scalar): 3x8x8 -> 64x[7][8]x2 (X)
    for (int idx = t; idx < 64 * 49 * 2; idx += 256) {
        int img = idx & 1, q = idx >> 1;
        int oc = q / 49, r = q % 49, y = r / 7, x = r % 7;
        float acc = b1[oc];
        const float* wv = w1 + oc * 12;
        #pragma unroll
        for (int ic = 0; ic < 3; ic++) {
            const float* ip = s_in + (ic * 64 + y * 8 + x) * 2 + img;
            acc += ip[0]*wv[0] + ip[2]*wv[1] + ip[16]*wv[2] + ip[18]*wv[3];
            wv += 4;
        }
        X[(oc * 56 + y * 8 + x) * 2 + img] = gelu_f(acc);
    }
    __syncthreads();

    // conv2: 64x7x7 -> 128x[6][8]x2 (Y, oc-stride 100). f32x2.
    {
        const int oc = t & 127, half = t >> 7, y0 = half * 3;
        ull acc[18];
        #pragma unroll
        for (int p = 0; p < 18; p++) acc[p] = 0ULL;
        for (int ic = 0; ic < 64; ic++) {
            const ull* wp = d_wp + WP2_OFF + ((oc * 64 + ic) << 2);
            LDW4;
            const float* Xc = X + (ic * 56 + y0 * 8) * 2;
            ull r0[8], r1[8];
            LDP8(r0, Xc);
            LDP8(r1, Xc + 16);
            CROW2(r0, r1, acc, 0, 6);
            LDP8(r0, Xc + 32);
            CROW2(r1, r0, acc, 1, 6);
            LDP8(r1, Xc + 48);
            CROW2(r0, r1, acc, 2, 6);
        }
        float bb = b2[oc];
        #pragma unroll
        for (int yy = 0; yy < 3; yy++)
            #pragma unroll
            for (int x = 0; x < 6; x++) {
                float lo, hi; UPK(acc[yy*6+x], lo, hi);
                *(ull*)&Y[oc * 100 + (y0 + yy) * 16 + 2 * x] =
                    pkf(gelu_f(lo + bb), gelu_f(hi + bb));
            }
    }
    __syncthreads();

    // conv3: 128x[6][8]x2 (Y) -> 256x[25]x2 (X). f32x2.
    {
        const int oc = t;
        ull acc[25];
        #pragma unroll
        for (int p = 0; p < 25; p++) acc[p] = 0ULL;
        for (int ic = 0; ic < 128; ic++) {
            const ull* wp = d_wp + WP3_OFF + ((oc * 128 + ic) << 2);
            LDW4;
            const float* Yc = Y + ic * 100;
            ull r0[6], r1[6];
            LDP6(r0, Yc);
            LDP6(r1, Yc + 16);
            CROW2(r0, r1, acc, 0, 5);
            LDP6(r0, Yc + 32);
            CROW2(r1, r0, acc, 1, 5);
            LDP6(r1, Yc + 48);
            CROW2(r0, r1, acc, 2, 5);
            LDP6(r0, Yc + 64);
            CROW2(r1, r0, acc, 3, 5);
            LDP6(r1, Yc + 80);
            CROW2(r0, r1, acc, 4, 5);
        }
        float bb = b3[oc];
        __syncthreads();
        #pragma unroll
        for (int p = 0; p < 25; p++) {
            float lo, hi; UPK(acc[p], lo, hi);
            *(ull*)&X[(oc * 25 + p) * 2] = pkf(gelu_f(lo + bb), gelu_f(hi + bb));
        }
    }
    __syncthreads();

    // primary caps: 256x[25]x2 (X) -> 96x[16]x2 (Y, g-stride 34). f32x2.
    if (t < 192) {
        const int g = t >> 1, half = t & 1, y0 = half * 2;
        ull acc[8];
        #pragma unroll
        for (int p = 0; p < 8; p++) acc[p] = 0ULL;
        for (int ic = 0; ic < 256; ic++) {
            const ull* wp = d_wp + WPP_OFF + ((g * 256 + ic) << 2);
            LDW4;
            const float* Xc = X + ic * 50 + y0 * 10;
            ull r0[5], r1[5];
            LDP5(r0, Xc);
            LDP5(r1, Xc + 10);
            CROW2(r0, r1, acc, 0, 4);
            LDP5(r0, Xc + 20);
            CROW2(r1, r0, acc, 1, 4);
        }
        float bb = pb[g];
        #pragma unroll
        for (int yy = 0; yy < 2; yy++)
            #pragma unroll
            for (int x = 0; x < 4; x++) {
                float lo, hi; UPK(acc[yy*4+x], lo, hi);
                *(ull*)&Y[g * 34 + ((y0 + yy) * 4 + x) * 2] = pkf(lo + bb, hi + bb);
            }
    }
    __syncthreads();

    // squash per (capsule, img); store fp16 u as [i][b][k]
    if (t < 192) {
        const int c = t >> 1, img = t & 1, b = b0 + img;
        const float* yp = Y + c * 34 + img;
        float n2 = 0.f;
        #pragma unroll
        for (int d = 0; d < 16; d++) { float v = yp[d * 2]; n2 += v * v; }
        float n = sqrtf(n2);
        float sc = (1.0f - expf(-n)) / (n + 1e-8f);
        __half2* up = (__half2*)(d_uh + ((size_t)c * BATCH + b) * 16);
        #pragma unroll
        for (int q = 0; q < 8; q++)
            up[q] = __floats2half2_rn(yp[4*q] * sc, yp[4*q + 2] * sc);
    }
}

// ---------------- 2) u_hat via tensor cores, smem-staged coalesced stores ------
#define STG_STRIDE 136
#define UHAT_SMEM (512 * 16 * 2 + 8 * 16 * STG_STRIDE * 2)
__global__ __launch_bounds__(256) void uhat_mma_kernel() {
    extern __shared__ __half hsmem[];
    __half* As = hsmem;
    const int i = blockIdx.y;
    const int n0 = blockIdx.x * 128;
    const int warp = threadIdx.x >> 5, lane = threadIdx.x & 31;
    __half* st = hsmem + 512 * 16 + warp * (16 * STG_STRIDE);

    {
        const uint4* src = (const uint4*)(d_uh + (size_t)i * BATCH * 16);
        uint4* dst = (uint4*)As;
        for (int t2 = threadIdx.x; t2 < 1024; t2 += 256) dst[t2] = src[t2];
    }
    __syncthreads();

    const int nrem = NTOT - n0;
    const int no = nrem >> 4;
    const int obase = n0 >> 4;
    const __half* Vb = d_vh + (size_t)i * NTOT * 16;

    unsigned bf0[16], bf1[16];
    #pragma unroll
    for (int tn = 0; tn < 16; tn++) {
        if (tn * 8 < nrem) {
            int n = n0 + tn * 8 + (lane >> 2);
            const __half* p = Vb + n * 16 + (lane & 3) * 2;
            bf0[tn] = *(const unsigned*)(p);
            bf1[tn] = *(const unsigned*)(p + 8);
        } else { bf0[tn] = 0u; bf1[tn] = 0u; }
    }

    #pragma unroll
    for (int mt = 0; mt < 4; mt++) {
        const int m0 = warp * 64 + mt * 16;
        const __half* ap = As + (m0 + (lane >> 2)) * 16 + (lane & 3) * 2;
        unsigned a0 = *(const unsigned*)(ap);
        unsigned a1 = *(const unsigned*)(ap + 8 * 16);
        unsigned a2 = *(const unsigned*)(ap + 8);
        unsigned a3 = *(const unsigned*)(ap + 8 * 16 + 8);
        const int rb = lane >> 2, col = 2 * (lane & 3);
        #pragma unroll
        for (int tn = 0; tn < 16; tn++) {
            if (tn * 8 < nrem) {
                float e0, e1, e2, e3;
                asm volatile(
                    "mma.sync.aligned.m16n8k16.row.col.f32.f16.f16.f32 "
                    "{%0,%1,%2,%3}, {%4,%5,%6,%7}, {%8,%9}, {%10,%11,%12,%13};"
                    : "=f"(e0), "=f"(e1), "=f"(e2), "=f"(e3)
                    : "r"(a0), "r"(a1), "r"(a2), "r"(a3),
                      "r"(bf0[tn]), "r"(bf1[tn]),
                      "f"(0.f), "f"(0.f), "f"(0.f), "f"(0.f));
                int c = tn * 8 + col;
                *(__half2*)&st[rb * STG_STRIDE + c]       = __floats2half2_rn(e0, e1);
                *(__half2*)&st[(rb + 8) * STG_STRIDE + c] = __floats2half2_rn(e2, e3);
            }
        }
        __syncwarp();
        #pragma unroll
        for (int q = 0; q < 8; q++) {
            int v = q * 32 + lane;
            int gr = v >> 1;
            int rb2 = gr & 15, ol = gr >> 4, h = v & 1;
            if (ol < no) {
                uint4 val = *(const uint4*)&st[rb2 * STG_STRIDE + ol * 16 + h * 8];
                *(uint4*)(d_uhat + ((size_t)((m0 + rb2) * NUM_CAPS + obase + ol) * 96
                                    + i) * 16 + h * 8) = val;
            }
        }
        __syncwarp();
    }
}

// ---------------- 3) routing ---------------------------------------------------
// staging: float4 gmem loads into 97-padded smem
#define SMAX_STAGE(SRCP) do { \
    const float4* _p4 = (const float4*)(SRCP); \
    for (int idx = t; idx < 4344; idx += 256) { \
        float4 v = _p4[idx]; \
        int r = idx / 24, c4 = (idx % 24) * 4; \
        float* row = sb + r * 97 + c4; \
        row[0] = v.x; row[1] = v.y; row[2] = v.z; row[3] = v.w; \
    } \
} while (0)

__global__ void softmax_first_kernel(const float* __restrict__ caps_b) {
    extern __shared__ float sb[];
    const int t = threadIdx.x;
    SMAX_STAGE(caps_b);
    __syncthreads();
    const int wid = t >> 5, lane = t & 31;
    for (int i = wid; i < 96; i += 8) {
        float m = -1e30f;
        for (int o = lane; o < NUM_CAPS; o += 32) m = fmaxf(m, sb[o * 97 + i]);
        #pragma unroll
        for (int s = 16; s; s >>= 1) m = fmaxf(m, __shfl_xor_sync(0xffffffffu, m, s));
        float s = 0.f;
        for (int o = lane; o < NUM_CAPS; o += 32) s += expf(sb[o * 97 + i] - m);
        #pragma unroll
        for (int sh = 16; sh; sh >>= 1) s += __shfl_xor_sync(0xffffffffu, s, sh);
        if (lane == 0) d_ms[i] = make_float2(m, 1.0f / s);
    }
}

__global__ void softmax3_kernel() {
    extern __shared__ float sb[];
    const int b = blockIdx.x, t = threadIdx.x;
    SMAX_STAGE(d_bl + (size_t)b * OI);
    __syncthreads();
    const int wid = t >> 5, lane = t & 31;
    for (int i = wid; i < 96; i += 8) {
        float m = -1e30f;
        for (int o = lane; o < NUM_CAPS; o += 32) m = fmaxf(m, sb[o * 97 + i]);
        #pragma unroll
        for (int s = 16; s; s >>= 1) m = fmaxf(m, __shfl_xor_sync(0xffffffffu, m, s));
        float s = 0.f;
        for (int o = lane; o < NUM_CAPS; o += 32) s += expf(sb[o * 97 + i] - m);
        #pragma unroll
        for (int sh = 16; sh; sh >>= 1) s += __shfl_xor_sync(0xffffffffu, s, sh);
        if (lane == 0) d_ms[b * 96 + i] = make_float2(m, 1.0f / s);
    }
}

template<bool FIRST, bool LAST>
__global__ __launch_bounds__(256) void route4_kernel(const float* __restrict__ caps_b) {
    __shared__ float incsh[8][96];
    const int wid = threadIdx.x >> 5, lane = threadIdx.x & 31;
    const int w = blockIdx.x * 8 + wid;
    const int b = w / NUM_CAPS;
    const uint4* up = (const uint4*)(d_uhat + (size_t)w * UHAT_TILE);
    float* blp = d_bl + (size_t)w * 96;

    float bl0, bl1, bl2;
    if (FIRST) {
        const int o = w - b * NUM_CAPS;
        const float* cbp = caps_b + o * 96;
        bl0 = cbp[lane]; bl1 = cbp[32 + lane]; bl2 = cbp[64 + lane];
    } else {
        bl0 = blp[lane]; bl1 = blp[32 + lane]; bl2 = blp[64 + lane];
    }
    const float2* msp = FIRST ? d_ms : (d_ms + b * 96);
    float2 ms0 = msp[lane], ms1 = msp[32 + lane], ms2 = msp[64 + lane];
    float c0 = expf(bl0 - ms0.x) * ms0.y;
    float c1 = expf(bl1 - ms1.x) * ms1.y;
    float c2 = expf(bl2 - ms2.x) * ms2.y;

    uint4 uv[6];
    float acc[8];
    #pragma unroll
    for (int q = 0; q < 8; q++) acc[q] = 0.f;
    #pragma unroll
    for (int j = 0; j < 6; j++) {
        uv[j] = up[j * 32 + lane];
        float cr = (j < 2) ? c0 : (j < 4) ? c1 : c2;
        float cv = __shfl_sync(0xffffffffu, cr, ((j & 1) << 4) + (lane >> 1));
        const __half2* h = (const __half2*)&uv[j];
        #pragma unroll
        for (int q = 0; q < 4; q++) {
            float2 f = __half22float2(h[q]);
            acc[2*q]   += cv * f.x;
            acc[2*q+1] += cv * f.y;
        }
    }
    #pragma unroll
    for (int m = 2; m <= 16; m <<= 1)
        #pragma unroll
        for (int q = 0; q < 8; q++)
            acc[q] += __shfl_xor_sync(0xffffffffu, acc[q], m);
    float sq = 0.f;
    #pragma unroll
    for (int q = 0; q < 8; q++) sq += acc[q] * acc[q];
    sq += __shfl_xor_sync(0xffffffffu, sq, 1);
    float n = sqrtf(sq);
    float sc = (1.0f - expf(-n)) / (n + 1e-8f);
    #pragma unroll
    for (int q = 0; q < 8; q++) acc[q] *= sc;

    if (LAST) {
        if (lane < 2) {
            float4* xp = (float4*)(d_x + (size_t)w * 16);
            xp[lane * 2 + 0] = make_float4(acc[0], acc[1], acc[2], acc[3]);
            xp[lane * 2 + 1] = make_float4(acc[4], acc[5], acc[6], acc[7]);
        }
    } else {
        #pragma unroll
        for (int j = 0; j < 6; j++) {
            const __half2* h = (const __half2*)&uv[j];
            float p = 0.f;
            #pragma unroll
            for (int q = 0; q < 4; q++) {
                float2 f = __half22float2(h[q]);
                p += acc[2*q] * f.x + acc[2*q+1] * f.y;
            }
            p += __shfl_xor_sync(0xffffffffu, p, 1);
            if (!(lane & 1)) incsh[wid][j * 16 + (lane >> 1)] = p;
        }
        __syncwarp();
        blp[lane]      = bl0 + incsh[wid][lane];
        blp[32 + lane] = bl1 + incsh[wid][32 + lane];
        blp[64 + lane] = bl2 + incsh[wid][64 + lane];
    }
}

// ---------------- 4) length, peaks, top-K, gather ------------------------------
__global__ void finalize_kernel(float* __restrict__ outL) {
    const int b = blockIdx.x, t = threadIdx.x;
    __shared__ float len[192], lnN[192], pk[192], red[256];
    float L = 0.f;
    if (t < NUM_CAPS) {
        const float* xp = d_x + ((size_t)b * NUM_CAPS + t) * 16;
        float n2 = 0.f;
        #pragma unroll
        for (int d = 0; d < 16; d++) { float v = xp[d]; n2 += v * v; }
        L = sqrtf(n2);
        len[t] = L;
    }
    red[t] = (t < NUM_CAPS) ? L : 0.f;
    __syncthreads();
    for (int s = 128; s > 0; s >>= 1) {
        if (t < s) red[t] += red[t + s];
        __syncthreads();
    }
    float tot = red[0];
    if (t < NUM_CAPS) {
        float ln = len[t] / (tot + 1e-8f);
        lnN[t] = ln;
        outL[b * NUM_CAPS + t] = ln;
    }
    __syncthreads();
    if (t < NUM_CAPS) {
        int lo = t - 5 > 0 ? t - 5 : 0;
        int hi = t + 5 < 180 ? t + 5 : 180;
        float m = -1e30f;
        for (int o = lo; o <= hi; o++) m = fmaxf(m, lnN[o]);
        pk[t] = (lnN[t] == m) ? lnN[t] : 0.f;
    }
    __syncthreads();
    if (t == 0) {
        int s0, s1, s2, s3;
        {
            int b0 = -1; float v0 = -1e30f;
            for (int o = 0; o < NUM_CAPS; o++)
                if (pk[o] > v0) { v0 = pk[o]; b0 = o; }
            pk[b0] = -1e30f; s0 = b0;
            int b1 = -1; float v1 = -1e30f;
            for (int o = 0; o < NUM_CAPS; o++)
                if (pk[o] > v1) { v1 = pk[o]; b1 = o; }
            pk[b1] = -1e30f; s1 = b1;
            int b2 = -1; float v2 = -1e30f;
            for (int o = 0; o < NUM_CAPS; o++)
                if (pk[o] > v2) { v2 = pk[o]; b2 = o; }
            pk[b2] = -1e30f; s2 = b2;
            int b3 = -1; float v3 = -1e30f;
            for (int o = 0; o < NUM_CAPS; o++)
                if (pk[o] > v3) { v3 = pk[o]; b3 = o; }
            s3 = b3;
        }
        int tmp;
        if (s0 > s1) { tmp = s0; s0 = s1; s1 = tmp; }
        if (s2 > s3) { tmp = s2; s2 = s3; s3 = tmp; }
        if (s0 > s2) { tmp = s0; s0 = s2; s2 = tmp; }
        if (s1 > s3) { tmp = s1; s1 = s3; s3 = tmp; }
        if (s1 > s2) { tmp = s1; s1 = s2; s2 = tmp; }
        pk[184] = __int_as_float(s0); pk[185] = __int_as_float(s1);
        pk[186] = __int_as_float(s2); pk[187] = __int_as_float(s3);
    }
    __syncthreads();
    if (t < 4 * 16) {
        int k = t >> 4, d = t & 15;
        int sel = __float_as_int(pk[184 + k]);
        if (d == 0) d_idx[b * KSEL + k] = sel;
        d_g[(b * KSEL + k) * 16 + d] = d_x[((size_t)b * NUM_CAPS + sel) * 16 + d];
    }
}

// ---------------- 5) MLP -------------------------------------------------------
__global__ void fc1_kernel(const float* __restrict__ w, const float* __restrict__ bias) {
    const int r = blockIdx.y;
    const int j = blockIdx.x * 256 + threadIdx.x;
    __shared__ float gr[16];
    __shared__ int base;
    if (threadIdx.x < 16) gr[threadIdx.x] = d_g[r * 16 + threadIdx.x];
    if (threadIdx.x == 0) base = d_idx[r] * 16;
    __syncthreads();
    float acc = bias[j];
    #pragma unroll
    for (int d = 0; d < 16; d++) acc += gr[d] * w[(size_t)(base + d) * 1024 + j];
    d_m0h[r * 1024 + j] = __float2half(gelu_f(acc));
}

#define MMA_ACC(CC, A0, A1, A2, A3, B0, B1) \
    asm volatile( \
        "mma.sync.aligned.m16n8k16.row.col.f32.f16.f16.f32 " \
        "{%0,%1,%2,%3}, {%4,%5,%6,%7}, {%8,%9}, {%10,%11,%12,%13};" \
        : "=f"(CC.x), "=f"(CC.y), "=f"(CC.z), "=f"(CC.w) \
        : "r"(A0), "r"(A1), "r"(A2), "r"(A3), "r"(B0), "r"(B1), \
          "f"(CC.x), "f"(CC.y), "f"(CC.z), "f"(CC.w))

#define DO_NT(NT, CLO, CHI) do { \
    const __half* _bp = &Bs[(warp & 3) * 32 + (NT) * 8 + (lane >> 2)][kk + (lane & 3) * 2]; \
    unsigned _b0 = *(const unsigned*)_bp; \
    unsigned _b1 = *(const unsigned*)(_bp + 8); \
    MMA_ACC(CLO, a00, a01, a02, a03, _b0, _b1); \
    MMA_ACC(CHI, a10, a11, a12, a13, _b0, _b1); \
} while (0)

#define EPI(CC, MT, NT) do { \
    int _n0 = bn + (warp & 3) * 32 + (NT) * 8 + (lane & 3) * 2; \
    float _b0v = bias[_n0], _b1v = bias[_n0 + 1]; \
    int _m1 = bm + (warp >> 2) * 32 + (MT) * 16 + (lane >> 2), _m2 = _m1 + 8; \
    float _v0 = CC.x + _b0v, _v1 = CC.y + _b1v, _v2 = CC.z + _b0v, _v3 = CC.w + _b1v; \
    if (ACT) { _v0 = gelu_f(_v0); _v1 = gelu_f(_v1); _v2 = gelu_f(_v2); _v3 = gelu_f(_v3); } \
    if (!TRANS) { \
        *(__half2*)&Ch[(size_t)_m1 * N + _n0] = __floats2half2_rn(_v0, _v1); \
        *(__half2*)&Ch[(size_t)_m2 * N + _n0] = __floats2half2_rn(_v2, _v3); \
    } else { \
        Cf[(size_t)(_m1 >> 2) * (N * 4) + _n0 * 4 + (_m1 & 3)]       = _v0; \
        Cf[(size_t)(_m1 >> 2) * (N * 4) + (_n0 + 1) * 4 + (_m1 & 3)] = _v1; \
        Cf[(size_t)(_m2 >> 2) * (N * 4) + _n0 * 4 + (_m2 & 3)]       = _v2; \
        Cf[(size_t)(_m2 >> 2) * (N * 4) + (_n0 + 1) * 4 + (_m2 & 3)] = _v3; \
    } \
} while (0)

template<int ACT, int TRANS, int SRC, int DST, int WOFF>
__global__ __launch_bounds__(256) void mlp_mma_kernel(
        const float* __restrict__ bias, float* __restrict__ Cf, int Kd, int N) {
    const __half* __restrict__ A  = SRC ? d_m1h : d_m0h;
    const __half* __restrict__ Wt = d_wt + WOFF;
    __half* __restrict__ Ch       = DST ? d_m1h : d_m0h;
    __shared__ __half As[64][40];
    __shared__ __half Bs[128][40];
    const int bm = blockIdx.y * 64, bn = blockIdx.x * 128;
    const int t = threadIdx.x, warp = t >> 5, lane = t & 31;
    float4 c0 = make_float4(0.f, 0.f, 0.f, 0.f), c1 = c0, c2 = c0, c3 = c0;
    float4 c4 = c0, c5 = c0, c6 = c0, c7 = c0;

    for (int k0 = 0; k0 < Kd; k0 += 32) {
        {
            int r = t >> 2, q = t & 3;
            *(uint4*)&As[r][q * 8] =
                *(const uint4*)&A[(size_t)(bm + r) * Kd + k0 + q * 8];
        }
        #pragma unroll
        for (int it = 0; it < 2; it++) {
            int l = t + it * 256;
            int r = l >> 2, q = l & 3;
            *(uint4*)&Bs[r][q * 8] =
                *(const uint4*)&Wt[(size_t)(bn + r) * Kd + k0 + q * 8];
        }
        __syncthreads();
        #pragma unroll
        for (int ks = 0; ks < 2; ks++) {
            const int kk = ks * 16;
            const __half* ap = &As[(warp >> 2) * 32 + (lane >> 2)][kk + (lane & 3) * 2];
            unsigned a00 = *(const unsigned*)ap;
            unsigned a01 = *(const unsigned*)(ap + 8 * 40);
            unsigned a02 = *(const unsigned*)(ap + 8);
            unsigned a03 = *(const unsigned*)(ap + 8 * 40 + 8);
            const __half* ap1 = ap + 16 * 40;
            unsigned a10 = *(const unsigned*)ap1;
            unsigned a11 = *(const unsigned*)(ap1 + 8 * 40);
            unsigned a12 = *(const unsigned*)(ap1 + 8);
            unsigned a13 = *(const unsigned*)(ap1 + 8 * 40 + 8);
            DO_NT(0, c0, c4);
            DO_NT(1, c1, c5);
            DO_NT(2, c2, c6);
            DO_NT(3, c3, c7);
        }
        __syncthreads();
    }

    EPI(c0, 0, 0); EPI(c1, 0, 1); EPI(c2, 0, 2); EPI(c3, 0, 3);
    EPI(c4, 1, 0); EPI(c5, 1, 1); EPI(c6, 1, 2); EPI(c7, 1, 3);
}

// ---------------- launch -------------------------------------------------------
extern "C" void kernel_launch(void* const* d_in, const int* in_sizes, int n_in,
                              void* d_out, int out_size) {
    const float* scm  = (const float*)d_in[0];
    const float* c1w = (const float*)d_in[2];  const float* c1b = (const float*)d_in[3];
    const float* c2w = (const float*)d_in[4];  const float* c2b = (const float*)d_in[5];
    const float* c3w = (const float*)d_in[6];  const float* c3b = (const float*)d_in[7];
    const float* pcw = (const float*)d_in[8];  const float* pcb = (const float*)d_in[9];
    const float* capsW = (const float*)d_in[10];
    const float* capsb = (const float*)d_in[11];
    const float* f1w = (const float*)d_in[12]; const float* f1b = (const float*)d_in[13];
    const float* f2w = (const float*)d_in[14]; const float* f2b = (const float*)d_in[15];
    const float* f3w = (const float*)d_in[16]; const float* f3b = (const float*)d_in[17];
    const float* f4w = (const float*)d_in[18]; const float* f4b = (const float*)d_in[19];
    const float* f5w = (const float*)d_in[20]; const float* f5b = (const float*)d_in[21];
    const float* hw  = (const float*)d_in[22]; const float* hb  = (const float*)d_in[23];

    float* outW = (float*)d_out;                       // [512, 128, 4]
    float* outL = outW + BATCH * 128 * KSEL;           // [512, 181]

    static int smem_set = 0;
    const int smax_smem = (NUM_CAPS * 97) * sizeof(float);
    if (!smem_set) {
        cudaFuncSetAttribute(softmax3_kernel,
                             cudaFuncAttributeMaxDynamicSharedMemorySize, smax_smem);
        cudaFuncSetAttribute(softmax_first_kernel,
                             cudaFuncAttributeMaxDynamicSharedMemorySize, smax_smem);
        cudaFuncSetAttribute(conv_stack_kernel,
                             cudaFuncAttributeMaxDynamicSharedMemorySize, CONV_SMEM);
        cudaFuncSetAttribute(uhat_mma_kernel,
                             cudaFuncAttributeMaxDynamicSharedMemorySize, UHAT_SMEM);
        smem_set = 1;
    }

    const int route_grid = BATCH * NUM_CAPS / 8;

    cwpack_kernel<<<(WP_TOTAL + 255) / 256, 256>>>(c2w, c3w, pcw);                   // 1
    wrepack_kernel<<<(NUM_CAPS * 1536 + 255) / 256, 256>>>(capsW);                   // 2
    softmax_first_kernel<<<1, 256, smax_smem>>>(capsb);                              // 3
    conv_stack_kernel<<<BATCH / 2, 256, CONV_SMEM>>>(scm, c1w, c1b, c2b, c3b, pcb);  // 4 (ncu)
    uhat_mma_kernel<<<dim3(23, 96), 256, UHAT_SMEM>>>();                             // 5
    wtrepack_kernel<<<dim3(32, 24), 256>>>(f2w, 1024, 768, OFF2);
    wtrepack_kernel<<<dim3(24, 16), 256>>>(f3w,  768, 512, OFF3);
    wtrepack_kernel<<<dim3(16, 16), 256>>>(f4w,  512, 512, OFF4);
    wtrepack_kernel<<<dim3(16,  8), 256>>>(f5w,  512, 256, OFF5);
    wtrepack_kernel<<<dim3( 8,  4), 256>>>(hw,   256, 128, OFFH);
    route4_kernel<true,  false><<<route_grid, 256>>>(capsb);
    softmax3_kernel<<<BATCH, 256, smax_smem>>>();
    route4_kernel<false, false><<<route_grid, 256>>>(capsb);
    softmax3_kernel<<<BATCH, 256, smax_smem>>>();
    route4_kernel<false, true ><<<route_grid, 256>>>(capsb);

    finalize_kernel<<<BATCH, 256>>>(outL);
    fc1_kernel<<<dim3(4, MLP_ROWS), 256>>>(f1w, f1b);
    mlp_mma_kernel<1, 0, 0, 1, OFF2><<<dim3(6, 32), 256>>>(f2b, nullptr, 1024, 768);
    mlp_mma_kernel<1, 0, 1, 0, OFF3><<<dim3(4, 32), 256>>>(f3b, nullptr,  768, 512);
    mlp_mma_kernel<1, 0, 0, 1, OFF4><<<dim3(4, 32), 256>>>(f4b, nullptr,  512, 512);
    mlp_mma_kernel<1, 0, 1, 0, OFF5><<<dim3(2, 32), 256>>>(f5b, nullptr,  512, 256);
    mlp_mma_kernel<0, 1, 0, 1, OFFH><<<dim3(1, 32), 256>>>(hb,  outW,     256, 128);
}